// round 1
// baseline (speedup 1.0000x reference)
#include <cuda_runtime.h>
#include <cuda_bf16.h>
#include <math.h>

#define Bn 4
#define Cn 512
#define Ln 4096

// Scratch: energy / attention in [b][i][j] layout (softmax axis j contiguous).
// 4*4096*4096 floats = 268 MB, static device global (allocation rules).
__device__ float g_E[(size_t)Bn * Ln * Ln];

// ---------------------------------------------------------------------------
// Kernel 1: energy[b,i,j] = (sum_c Q[b,c,i]*K[b,c,j]) / sqrt(C) + log(mask[b,j]+1e-6)
// TN SGEMM: A = Q (C x L, i contiguous), B = K (C x L, j contiguous).
// 128x128 tile, BK=16, 256 threads, 8x8 per thread.
// ---------------------------------------------------------------------------
__global__ __launch_bounds__(256) void gemm_qk_kernel(
    const float* __restrict__ Q, const float* __restrict__ Kt,
    const float* __restrict__ mask)
{
    const int b  = blockIdx.z;
    const int j0 = blockIdx.x * 128;
    const int i0 = blockIdx.y * 128;
    const float* Qb = Q  + (size_t)b * Cn * Ln;
    const float* Kb = Kt + (size_t)b * Cn * Ln;
    float*       Eb = g_E + (size_t)b * Ln * Ln;
    const float* mrow = mask + (size_t)b * Ln;

    __shared__ float As[16][128];
    __shared__ float Bs[16][128];

    const int tid = threadIdx.x;
    const int tx = tid & 15;        // 0..15 -> n (j) direction
    const int ty = tid >> 4;        // 0..15 -> m (i) direction

    float acc[8][8];
#pragma unroll
    for (int m = 0; m < 8; m++)
#pragma unroll
        for (int n = 0; n < 8; n++) acc[m][n] = 0.0f;

    for (int k0 = 0; k0 < Cn; k0 += 16) {
#pragma unroll
        for (int t = 0; t < 2; t++) {
            int f   = tid + t * 256;        // 0..511
            int row = f >> 5;               // 0..15
            int col = (f & 31) << 2;        // 0..124
            *(float4*)&As[row][col] = *(const float4*)&Qb[(size_t)(k0 + row) * Ln + i0 + col];
            *(float4*)&Bs[row][col] = *(const float4*)&Kb[(size_t)(k0 + row) * Ln + j0 + col];
        }
        __syncthreads();
#pragma unroll
        for (int k = 0; k < 16; k++) {
            float a[8], bb[8];
            *(float4*)&a[0]  = *(float4*)&As[k][ty * 8];
            *(float4*)&a[4]  = *(float4*)&As[k][ty * 8 + 4];
            *(float4*)&bb[0] = *(float4*)&Bs[k][tx * 8];
            *(float4*)&bb[4] = *(float4*)&Bs[k][tx * 8 + 4];
#pragma unroll
            for (int m = 0; m < 8; m++)
#pragma unroll
                for (int n = 0; n < 8; n++) acc[m][n] += a[m] * bb[n];
        }
        __syncthreads();
    }

    const float scale = 1.0f / sqrtf((float)Cn);
    float lm[8];
#pragma unroll
    for (int n = 0; n < 8; n++)
        lm[n] = logf(mrow[j0 + tx * 8 + n] + 1e-6f);

#pragma unroll
    for (int m = 0; m < 8; m++) {
        const int i = i0 + ty * 8 + m;
        float r[8];
#pragma unroll
        for (int n = 0; n < 8; n++) r[n] = acc[m][n] * scale + lm[n];
        *(float4*)&Eb[(size_t)i * Ln + j0 + tx * 8]     = *(float4*)&r[0];
        *(float4*)&Eb[(size_t)i * Ln + j0 + tx * 8 + 4] = *(float4*)&r[4];
    }
}

// ---------------------------------------------------------------------------
// Kernel 2: in-place row softmax over j, then multiply by mask[b,j].
// One block (256 threads) per (b, i) row of 4096 elements.
// ---------------------------------------------------------------------------
__global__ __launch_bounds__(256) void softmax_mask_kernel(const float* __restrict__ mask)
{
    const int b = blockIdx.y;
    const int i = blockIdx.x;
    float* row = g_E + ((size_t)b * Ln + i) * Ln;
    const float* mrow = mask + (size_t)b * Ln;
    const int tid = threadIdx.x;

    __shared__ float red[8];

    float v[16];
    float mx = -3.0e38f;
#pragma unroll
    for (int t = 0; t < 16; t++) {
        v[t] = row[t * 256 + tid];
        mx = fmaxf(mx, v[t]);
    }
#pragma unroll
    for (int o = 16; o > 0; o >>= 1)
        mx = fmaxf(mx, __shfl_xor_sync(0xffffffffu, mx, o));
    if ((tid & 31) == 0) red[tid >> 5] = mx;
    __syncthreads();
    if (tid < 32) {
        float x = (tid < 8) ? red[tid] : -3.0e38f;
#pragma unroll
        for (int o = 4; o > 0; o >>= 1)
            x = fmaxf(x, __shfl_xor_sync(0xffffffffu, x, o));
        if (tid == 0) red[0] = x;
    }
    __syncthreads();
    mx = red[0];
    __syncthreads();

    float s = 0.0f;
#pragma unroll
    for (int t = 0; t < 16; t++) {
        v[t] = expf(v[t] - mx);
        s += v[t];
    }
#pragma unroll
    for (int o = 16; o > 0; o >>= 1)
        s += __shfl_xor_sync(0xffffffffu, s, o);
    if ((tid & 31) == 0) red[tid >> 5] = s;
    __syncthreads();
    if (tid < 32) {
        float x = (tid < 8) ? red[tid] : 0.0f;
#pragma unroll
        for (int o = 4; o > 0; o >>= 1)
            x += __shfl_xor_sync(0xffffffffu, x, o);
        if (tid == 0) red[0] = x;
    }
    __syncthreads();
    const float inv = 1.0f / red[0];

#pragma unroll
    for (int t = 0; t < 16; t++) {
        const int j = t * 256 + tid;
        row[j] = v[t] * inv * mrow[j];
    }
}

// ---------------------------------------------------------------------------
// Kernel 3: attT[b,j,i] = att[b,i,j] (tiled transpose into d_out).
// ---------------------------------------------------------------------------
__global__ __launch_bounds__(256) void transpose_kernel(float* __restrict__ AT)
{
    __shared__ float tile[32][33];
    const int b = blockIdx.z;
    const float* Ab = g_E + (size_t)b * Ln * Ln;
    float*       Tb = AT  + (size_t)b * Ln * Ln;

    const int xIn = blockIdx.x * 32 + threadIdx.x;   // j
    const int yIn = blockIdx.y * 32 + threadIdx.y;   // i
#pragma unroll
    for (int r = 0; r < 32; r += 8)
        tile[threadIdx.y + r][threadIdx.x] = Ab[(size_t)(yIn + r) * Ln + xIn];
    __syncthreads();
    const int xOut = blockIdx.y * 32 + threadIdx.x;  // i
    const int yOut = blockIdx.x * 32 + threadIdx.y;  // j
#pragma unroll
    for (int r = 0; r < 32; r += 8)
        Tb[(size_t)(yOut + r) * Ln + xOut] = tile[threadIdx.x][threadIdx.y + r];
}

// ---------------------------------------------------------------------------
// Kernel 4: out[b,c,i] = sum_j V[b,c,j] * attT[b,j,i].
// TN SGEMM: A = V (c rows, j cols; transpose-on-load), B = attT (j rows, i cols).
// ---------------------------------------------------------------------------
__global__ __launch_bounds__(256) void gemm_pv_kernel(
    const float* __restrict__ V, const float* __restrict__ P,
    float* __restrict__ out)
{
    const int b  = blockIdx.z;
    const int i0 = blockIdx.x * 128;
    const int c0 = blockIdx.y * 128;
    const float* Vb = V + (size_t)b * Cn * Ln;
    const float* Pb = P + (size_t)b * Ln * Ln;
    float*       Ob = out + (size_t)b * Cn * Ln;

    __shared__ float As[16][132];   // padded (transpose-on-load stores)
    __shared__ float Bs[16][128];

    const int tid = threadIdx.x;
    const int tx = tid & 15;        // n (i) direction
    const int ty = tid >> 4;        // m (c) direction

    float acc[8][8];
#pragma unroll
    for (int m = 0; m < 8; m++)
#pragma unroll
        for (int n = 0; n < 8; n++) acc[m][n] = 0.0f;

    for (int k0 = 0; k0 < Ln; k0 += 16) {
#pragma unroll
        for (int t = 0; t < 2; t++) {
            int f  = tid + t * 256;            // 0..511
            // A: rows c0+r (128), cols k0 + c4..c4+3 (16); store transposed
            int r  = f >> 2;                   // 0..127
            int c4 = (f & 3) << 2;             // 0,4,8,12
            float4 va = *(const float4*)&Vb[(size_t)(c0 + r) * Ln + k0 + c4];
            As[c4 + 0][r] = va.x;
            As[c4 + 1][r] = va.y;
            As[c4 + 2][r] = va.z;
            As[c4 + 3][r] = va.w;
            // B: rows k0+rb (16), cols i0 + cb..cb+3 (128)
            int rb = f >> 5;
            int cb = (f & 31) << 2;
            *(float4*)&Bs[rb][cb] = *(const float4*)&Pb[(size_t)(k0 + rb) * Ln + i0 + cb];
        }
        __syncthreads();
#pragma unroll
        for (int k = 0; k < 16; k++) {
            float a[8], bb[8];
            *(float4*)&a[0]  = *(float4*)&As[k][ty * 8];
            *(float4*)&a[4]  = *(float4*)&As[k][ty * 8 + 4];
            *(float4*)&bb[0] = *(float4*)&Bs[k][tx * 8];
            *(float4*)&bb[4] = *(float4*)&Bs[k][tx * 8 + 4];
#pragma unroll
            for (int m = 0; m < 8; m++)
#pragma unroll
                for (int n = 0; n < 8; n++) acc[m][n] += a[m] * bb[n];
        }
        __syncthreads();
    }

#pragma unroll
    for (int m = 0; m < 8; m++) {
        const int c = c0 + ty * 8 + m;
        *(float4*)&Ob[(size_t)c * Ln + i0 + tx * 8]     = *(float4*)&acc[m][0];
        *(float4*)&Ob[(size_t)c * Ln + i0 + tx * 8 + 4] = *(float4*)&acc[m][4];
    }
}

// ---------------------------------------------------------------------------
extern "C" void kernel_launch(void* const* d_in, const int* in_sizes, int n_in,
                              void* d_out, int out_size)
{
    const float* Q    = (const float*)d_in[0];
    const float* Kt   = (const float*)d_in[1];
    const float* V    = (const float*)d_in[2];
    const float* mask = (const float*)d_in[3];

    float* out  = (float*)d_out;                       // (B, C, L)
    float* attT = out + (size_t)Bn * Cn * Ln;          // (B, L, L) transposed attention

    gemm_qk_kernel<<<dim3(Ln / 128, Ln / 128, Bn), 256>>>(Q, Kt, mask);
    softmax_mask_kernel<<<dim3(Ln, Bn), 256>>>(mask);
    transpose_kernel<<<dim3(Ln / 32, Ln / 32, Bn), dim3(32, 8)>>>(attT);
    gemm_pv_kernel<<<dim3(Ln / 128, Cn / 128, Bn), 256>>>(V, attT, out);
}

// round 3
// speedup vs baseline: 2.2514x; 2.2514x over previous
#include <cuda_runtime.h>
#include <cuda_bf16.h>
#include <math.h>
#include <stdint.h>

#define Bn 4
#define Cn 512
#define Ln 4096

// ---------------------------------------------------------------------------
// Scratch (static device globals; no allocation allowed)
// ---------------------------------------------------------------------------
__device__ float g_E[(size_t)Bn * Ln * Ln];                    // energy fp32 [b][i][j]
__device__ __nv_bfloat16 g_Qt_hi[(size_t)Bn * Ln * Cn];        // Q^T  [b][i][c]
__device__ __nv_bfloat16 g_Qt_lo[(size_t)Bn * Ln * Cn];
__device__ __nv_bfloat16 g_Kt_hi[(size_t)Bn * Ln * Cn];        // K^T  [b][j][c]
__device__ __nv_bfloat16 g_Kt_lo[(size_t)Bn * Ln * Cn];
__device__ __nv_bfloat16 g_V_hi[(size_t)Bn * Cn * Ln];         // V    [b][c][j]
__device__ __nv_bfloat16 g_V_lo[(size_t)Bn * Cn * Ln];
__device__ __nv_bfloat16 g_P_hi[(size_t)Bn * Ln * Ln];         // att  [b][i][j]
__device__ __nv_bfloat16 g_P_lo[(size_t)Bn * Ln * Ln];

// ---------------------------------------------------------------------------
// Base-ISA helpers (compute_103-safe: ldmatrix / mma.sync / cp.async)
// ---------------------------------------------------------------------------
__device__ __forceinline__ uint32_t smem_u32(const void* p) {
    uint32_t a;
    asm("{ .reg .u64 t; cvta.to.shared.u64 t, %1; cvt.u32.u64 %0, t; }" : "=r"(a) : "l"(p));
    return a;
}
__device__ __forceinline__ void ldsm_x4(uint32_t addr, uint32_t r[4]) {
    asm volatile("ldmatrix.sync.aligned.m8n8.x4.shared.b16 {%0,%1,%2,%3}, [%4];"
                 : "=r"(r[0]), "=r"(r[1]), "=r"(r[2]), "=r"(r[3]) : "r"(addr));
}
__device__ __forceinline__ void mma_bf16(float d[4], const uint32_t a[4], const uint32_t b[2]) {
    asm volatile("mma.sync.aligned.m16n8k16.row.col.f32.bf16.bf16.f32 "
                 "{%0,%1,%2,%3}, {%4,%5,%6,%7}, {%8,%9}, {%0,%1,%2,%3};"
                 : "+f"(d[0]), "+f"(d[1]), "+f"(d[2]), "+f"(d[3])
                 : "r"(a[0]), "r"(a[1]), "r"(a[2]), "r"(a[3]), "r"(b[0]), "r"(b[1]));
}
#define CP16(d, s) asm volatile("cp.async.cg.shared.global [%0], [%1], 16;" :: "r"(d), "l"(s))
#define CP_COMMIT() asm volatile("cp.async.commit_group;" ::: "memory")
#define CP_WAIT1()  asm volatile("cp.async.wait_group 1;" ::: "memory")
#define CP_WAIT0()  asm volatile("cp.async.wait_group 0;" ::: "memory")

__device__ __forceinline__ void split_bf16(float x, __nv_bfloat16& h, __nv_bfloat16& l) {
    h = __float2bfloat16(x);
    l = __float2bfloat16(x - __bfloat162float(h));
}

// ---------------------------------------------------------------------------
// smem geometry: 4 tiles (Ah, Al, Bh, Bl), each 128 rows x 32 bf16, row
// stride padded to 80 B (conflict-free ldmatrix). Double buffered.
// ---------------------------------------------------------------------------
#define ROWB 80
#define TILE_B (128 * ROWB)        // 10240
#define OFF_AH 0
#define OFF_AL (1 * TILE_B)
#define OFF_BH (2 * TILE_B)
#define OFF_BL (3 * TILE_B)
#define BUF_B  (4 * TILE_B)        // 40960
#define LM_OFF (2 * BUF_B)         // 81920
#define SMEM_BYTES (2 * BUF_B + 512)

// ---------------------------------------------------------------------------
// bf16x3 tensor-core GEMM, 128x128 tile, BK=32, 256 threads, double buffer.
// FIRST: E[i][j] = (Qt[i][:] . Kt[j][:]) * scale + logmask[j]    (K = 512)
// !FIRST: out[c][i] = V[c][:] . P[i][:]                          (K = 4096)
// ---------------------------------------------------------------------------
template <bool FIRST>
__global__ __launch_bounds__(256) void mma_gemm_kernel(float* __restrict__ Dout,
                                                       const float* __restrict__ mask)
{
    constexpr int KTOT = FIRST ? Cn : Ln;
    constexpr int LD   = FIRST ? Cn : Ln;       // K-stride of A and B rows
    constexpr int NIT  = KTOT / 32;

    extern __shared__ char smem[];
    const uint32_t sbase = smem_u32(smem);
    const int tid = threadIdx.x;
    const int b = blockIdx.z;
    const int n0 = blockIdx.x * 128;
    const int m0 = blockIdx.y * 128;

    const __nv_bfloat16* Ah = (FIRST ? g_Qt_hi : g_V_hi) + ((size_t)b * (FIRST ? Ln : Cn) + m0) * LD;
    const __nv_bfloat16* Al = (FIRST ? g_Qt_lo : g_V_lo) + ((size_t)b * (FIRST ? Ln : Cn) + m0) * LD;
    const __nv_bfloat16* Bh = (FIRST ? g_Kt_hi : g_P_hi) + ((size_t)b * Ln + n0) * LD;
    const __nv_bfloat16* Bl = (FIRST ? g_Kt_lo : g_P_lo) + ((size_t)b * Ln + n0) * LD;
    float* D = (FIRST ? g_E : Dout) + (size_t)b * (FIRST ? Ln : Cn) * Ln;

    float* lmp = (float*)(smem + LM_OFF);
    if (FIRST && tid < 128)
        lmp[tid] = logf(mask[(size_t)b * Ln + n0 + tid] + 1e-6f);

    const int lane = tid & 31, wid = tid >> 5;
    const int wm = wid & 3, wn = wid >> 2;         // warp tile: 32 (m) x 64 (n)
    const int quad = lane >> 3, qj = lane & 7;
    const int a_row = (quad & 1) * 8 + qj;         // within m16
    const int a_kb  = (quad >> 1) * 16;            // byte offset within k16 row
    const int b_row = (quad >> 1) * 8 + qj;        // within n16
    const int b_kb  = (quad & 1) * 16;

    float acc[2][8][4];
#pragma unroll
    for (int fm = 0; fm < 2; fm++)
#pragma unroll
        for (int fn = 0; fn < 8; fn++)
#pragma unroll
            for (int e = 0; e < 4; e++) acc[fm][fn][e] = 0.0f;

    // ---- loader: one BK=32 slab into buffer `buf` --------------------------
    auto load_slab = [&](int buf, int it) {
        const uint32_t bb = sbase + buf * BUF_B;
        const int k0 = it * 32;
#pragma unroll
        for (int t = 0; t < 2; t++) {
            int f = t * 256 + tid;                 // 0..511
            int row = f >> 2, ch = f & 3;          // 128 rows x 4 x 16B
            uint32_t doff = row * ROWB + ch * 16;
            size_t soff = (size_t)row * LD + k0 + ch * 8;
            CP16(bb + OFF_AH + doff, Ah + soff);
            CP16(bb + OFF_AL + doff, Al + soff);
            CP16(bb + OFF_BH + doff, Bh + soff);
            CP16(bb + OFF_BL + doff, Bl + soff);
        }
        CP_COMMIT();
    };

    load_slab(0, 0);

    for (int it = 0; it < NIT; it++) {
        const int buf = it & 1;
        if (it + 1 < NIT) { load_slab(buf ^ 1, it + 1); CP_WAIT1(); }
        else              { CP_WAIT0(); }
        __syncthreads();

        const uint32_t bb = sbase + buf * BUF_B;
#pragma unroll
        for (int ks = 0; ks < 2; ks++) {
            uint32_t ah[2][4], al[2][4];
#pragma unroll
            for (int fm = 0; fm < 2; fm++) {
                uint32_t r = (wm * 32 + fm * 16 + a_row) * ROWB + ks * 32 + a_kb;
                ldsm_x4(bb + OFF_AH + r, ah[fm]);
                ldsm_x4(bb + OFF_AL + r, al[fm]);
            }
#pragma unroll
            for (int h = 0; h < 2; h++) {
                uint32_t bh[4][2], bl[4][2];
#pragma unroll
                for (int g = 0; g < 2; g++) {
                    uint32_t r = (wn * 64 + h * 32 + g * 16 + b_row) * ROWB + ks * 32 + b_kb;
                    uint32_t t4[4];
                    ldsm_x4(bb + OFF_BH + r, t4);
                    bh[g * 2][0] = t4[0]; bh[g * 2][1] = t4[1];
                    bh[g * 2 + 1][0] = t4[2]; bh[g * 2 + 1][1] = t4[3];
                    ldsm_x4(bb + OFF_BL + r, t4);
                    bl[g * 2][0] = t4[0]; bl[g * 2][1] = t4[1];
                    bl[g * 2 + 1][0] = t4[2]; bl[g * 2 + 1][1] = t4[3];
                }
#pragma unroll
                for (int fm = 0; fm < 2; fm++)
#pragma unroll
                    for (int fl = 0; fl < 4; fl++) {
                        int fn = h * 4 + fl;
                        mma_bf16(acc[fm][fn], ah[fm], bh[fl]);
                        mma_bf16(acc[fm][fn], ah[fm], bl[fl]);
                        mma_bf16(acc[fm][fn], al[fm], bh[fl]);
                    }
            }
        }
        __syncthreads();
    }

    // ---- epilogue -----------------------------------------------------------
    const float scale = 0.04419417382415922f;      // 1/sqrt(512)
#pragma unroll
    for (int fm = 0; fm < 2; fm++)
#pragma unroll
        for (int fn = 0; fn < 8; fn++) {
            int r0 = m0 + wm * 32 + fm * 16 + (lane >> 2);
            int cl = wn * 64 + fn * 8 + (lane & 3) * 2;   // local col
            float v0 = acc[fm][fn][0], v1 = acc[fm][fn][1];
            float v2 = acc[fm][fn][2], v3 = acc[fm][fn][3];
            if (FIRST) {
                v0 = v0 * scale + lmp[cl];     v1 = v1 * scale + lmp[cl + 1];
                v2 = v2 * scale + lmp[cl];     v3 = v3 * scale + lmp[cl + 1];
            }
            *(float2*)&D[(size_t)r0 * Ln + n0 + cl]       = make_float2(v0, v1);
            *(float2*)&D[(size_t)(r0 + 8) * Ln + n0 + cl] = make_float2(v2, v3);
        }
}

// ---------------------------------------------------------------------------
// Convert + transpose Q,K: [b][C][L] fp32 -> [b][L][C] bf16 hi/lo
// ---------------------------------------------------------------------------
template <bool ISQ>
__global__ void convT_kernel(const float* __restrict__ X)
{
    __shared__ float tile[32][33];
    const int b = blockIdx.z, l0 = blockIdx.x * 32, c0 = blockIdx.y * 32;
    const int tx = threadIdx.x, ty = threadIdx.y;
#pragma unroll
    for (int r = 0; r < 32; r += 8)
        tile[ty + r][tx] = X[((size_t)b * Cn + c0 + ty + r) * Ln + l0 + tx];
    __syncthreads();
    __nv_bfloat16* Hi = ISQ ? g_Qt_hi : g_Kt_hi;
    __nv_bfloat16* Lo = ISQ ? g_Qt_lo : g_Kt_lo;
#pragma unroll
    for (int r = 0; r < 32; r += 8) {
        float v = tile[tx][ty + r];
        __nv_bfloat16 h, l; split_bf16(v, h, l);
        size_t idx = ((size_t)b * Ln + l0 + ty + r) * Cn + c0 + tx;
        Hi[idx] = h; Lo[idx] = l;
    }
}

// Convert V elementwise: fp32 -> bf16 hi/lo (same [b][C][L] layout)
__global__ void convV_kernel(const float* __restrict__ V)
{
    size_t idx = ((size_t)blockIdx.x * 256 + threadIdx.x) * 2;
    float2 v = *(const float2*)(V + idx);
    __nv_bfloat16 h0, l0, h1, l1;
    split_bf16(v.x, h0, l0); split_bf16(v.y, h1, l1);
    *(__nv_bfloat162*)(g_V_hi + idx) = __nv_bfloat162(h0, h1);
    *(__nv_bfloat162*)(g_V_lo + idx) = __nv_bfloat162(l0, l1);
}

// ---------------------------------------------------------------------------
// Row softmax over j + mask multiply; emits att as bf16 hi/lo [b][i][j]
// ---------------------------------------------------------------------------
__global__ __launch_bounds__(256) void softmax_mask_kernel(const float* __restrict__ mask)
{
    const int b = blockIdx.y, i = blockIdx.x;
    const size_t rowbase = ((size_t)b * Ln + i) * Ln;
    const float* row = g_E + rowbase;
    const float* mrow = mask + (size_t)b * Ln;
    const int tid = threadIdx.x;
    __shared__ float red[8];

    float v[16];
    float mx = -3.0e38f;
#pragma unroll
    for (int t = 0; t < 16; t++) { v[t] = row[t * 256 + tid]; mx = fmaxf(mx, v[t]); }
#pragma unroll
    for (int o = 16; o > 0; o >>= 1) mx = fmaxf(mx, __shfl_xor_sync(0xffffffffu, mx, o));
    if ((tid & 31) == 0) red[tid >> 5] = mx;
    __syncthreads();
    if (tid < 32) {
        float x = (tid < 8) ? red[tid] : -3.0e38f;
#pragma unroll
        for (int o = 4; o > 0; o >>= 1) x = fmaxf(x, __shfl_xor_sync(0xffffffffu, x, o));
        if (tid == 0) red[0] = x;
    }
    __syncthreads();
    mx = red[0];
    __syncthreads();

    float s = 0.0f;
#pragma unroll
    for (int t = 0; t < 16; t++) { v[t] = expf(v[t] - mx); s += v[t]; }
#pragma unroll
    for (int o = 16; o > 0; o >>= 1) s += __shfl_xor_sync(0xffffffffu, s, o);
    if ((tid & 31) == 0) red[tid >> 5] = s;
    __syncthreads();
    if (tid < 32) {
        float x = (tid < 8) ? red[tid] : 0.0f;
#pragma unroll
        for (int o = 4; o > 0; o >>= 1) x += __shfl_xor_sync(0xffffffffu, x, o);
        if (tid == 0) red[0] = x;
    }
    __syncthreads();
    const float inv = 1.0f / red[0];

#pragma unroll
    for (int t = 0; t < 16; t++) {
        const int j = t * 256 + tid;
        float val = v[t] * inv * mrow[j];
        __nv_bfloat16 h, l; split_bf16(val, h, l);
        g_P_hi[rowbase + j] = h;
        g_P_lo[rowbase + j] = l;
    }
}

// ---------------------------------------------------------------------------
// attT[b][j][i] = att[b][i][j]   (output-only transpose, hi+lo reconstruct)
// ---------------------------------------------------------------------------
__global__ void transP_kernel(float* __restrict__ AT)
{
    __shared__ float tile[32][33];
    const int b = blockIdx.z, j0 = blockIdx.x * 32, i0 = blockIdx.y * 32;
    const int tx = threadIdx.x, ty = threadIdx.y;
    float* Tb = AT + (size_t)b * Ln * Ln;
#pragma unroll
    for (int r = 0; r < 32; r += 8) {
        size_t idx = ((size_t)b * Ln + i0 + ty + r) * Ln + j0 + tx;
        tile[ty + r][tx] = __bfloat162float(g_P_hi[idx]) + __bfloat162float(g_P_lo[idx]);
    }
    __syncthreads();
#pragma unroll
    for (int r = 0; r < 32; r += 8)
        Tb[(size_t)(j0 + ty + r) * Ln + i0 + tx] = tile[tx][ty + r];
}

// ---------------------------------------------------------------------------
extern "C" void kernel_launch(void* const* d_in, const int* in_sizes, int n_in,
                              void* d_out, int out_size)
{
    const float* Q    = (const float*)d_in[0];
    const float* Kt   = (const float*)d_in[1];
    const float* V    = (const float*)d_in[2];
    const float* mask = (const float*)d_in[3];

    float* out  = (float*)d_out;                   // (B, C, L)
    float* attT = out + (size_t)Bn * Cn * Ln;      // (B, L, L)

    cudaFuncSetAttribute(mma_gemm_kernel<true>,
                         cudaFuncAttributeMaxDynamicSharedMemorySize, SMEM_BYTES);
    cudaFuncSetAttribute(mma_gemm_kernel<false>,
                         cudaFuncAttributeMaxDynamicSharedMemorySize, SMEM_BYTES);

    convT_kernel<true><<<dim3(Ln / 32, Cn / 32, Bn), dim3(32, 8)>>>(Q);
    convT_kernel<false><<<dim3(Ln / 32, Cn / 32, Bn), dim3(32, 8)>>>(Kt);
    convV_kernel<<<(int)(((size_t)Bn * Cn * Ln) / 512), 256>>>(V);

    mma_gemm_kernel<true><<<dim3(Ln / 128, Ln / 128, Bn), 256, SMEM_BYTES>>>(nullptr, mask);
    softmax_mask_kernel<<<dim3(Ln, Bn), 256>>>(mask);
    mma_gemm_kernel<false><<<dim3(Ln / 128, Cn / 128, Bn), 256, SMEM_BYTES>>>(out, nullptr);
    transP_kernel<<<dim3(Ln / 32, Ln / 32, Bn), dim3(32, 8)>>>(attT);
}